// round 4
// baseline (speedup 1.0000x reference)
#include <cuda_runtime.h>
#include <cuda_bf16.h>

#define EMB 16
#define MAXN 200000
#define MAXE 4000000

// Scratch (device globals — no allocation allowed)
__device__ float4 g_left_t[MAXN * 4];    // [N_LEFT, 16]  transformed left
__device__ float4 g_right_t[MAXN * 4];   // [N_RIGHT, 16] transformed right
__device__ float4 g_agg[MAXN * 4];       // [N_RIGHT, 16] sum of relu(pre)
__device__ float  g_deg[MAXN];           // per-right-node degree (float)

// ---------------------------------------------------------------------------
// Kernel 1: node transforms.  left_t = L @ W_left.T + b_left ;  right_t = R @ W_right.T
// One thread per node (left nodes first, then right nodes).
// ---------------------------------------------------------------------------
__global__ void node_transform_kernel(const float4* __restrict__ left,
                                      const float4* __restrict__ right,
                                      const float* __restrict__ W_left,
                                      const float* __restrict__ b_left,
                                      const float* __restrict__ W_right,
                                      int n_left, int n_right) {
    __shared__ float sWl[EMB * EMB];
    __shared__ float sWr[EMB * EMB];
    __shared__ float sbl[EMB];
    for (int i = threadIdx.x; i < EMB * EMB; i += blockDim.x) {
        sWl[i] = W_left[i];
        sWr[i] = W_right[i];
    }
    if (threadIdx.x < EMB) sbl[threadIdx.x] = b_left[threadIdx.x];
    __syncthreads();

    int t = blockIdx.x * blockDim.x + threadIdx.x;
    if (t >= n_left + n_right) return;

    bool is_left = (t < n_left);
    int node = is_left ? t : (t - n_left);
    const float4* src = is_left ? (left + (size_t)node * 4) : (right + (size_t)node * 4);
    float4* dst = is_left ? (g_left_t + (size_t)node * 4) : (g_right_t + (size_t)node * 4);
    const float* W = is_left ? sWl : sWr;

    float x[EMB];
#pragma unroll
    for (int q = 0; q < 4; q++) {
        float4 v = src[q];
        x[4 * q + 0] = v.x; x[4 * q + 1] = v.y; x[4 * q + 2] = v.z; x[4 * q + 3] = v.w;
    }

#pragma unroll
    for (int q = 0; q < 4; q++) {
        float acc[4];
#pragma unroll
        for (int c = 0; c < 4; c++) {
            int j = 4 * q + c;
            float a = is_left ? sbl[j] : 0.0f;
#pragma unroll
            for (int k = 0; k < EMB; k++) a = fmaf(x[k], W[j * EMB + k], a);
            acc[c] = a;
        }
        float4 y;
        y.x = acc[0]; y.y = acc[1]; y.z = acc[2]; y.w = acc[3];
        dst[q] = y;
    }
}

// ---------------------------------------------------------------------------
// Kernel 2: edge kernel.  4 lanes per edge; lane j handles float4 chunk j.
//   pre = left_t[li] + w_e * W_edge + right_t[ri]  ->  relu  ->  red.add into agg[ri]
//   lane 0 also bumps degree.
//   NOTE: edge_indices is int32 on device (JAX x64 disabled downcasts int64).
// ---------------------------------------------------------------------------
__global__ void edge_kernel(const int* __restrict__ eidx,        // [2, E] int32
                            const float* __restrict__ efeat,     // [E]
                            const float4* __restrict__ W_edge4,  // 16 floats = 4 x float4
                            int E) {
    long long t = (long long)blockIdx.x * blockDim.x + threadIdx.x;
    int e = (int)(t >> 2);
    if (e >= E) return;
    int j = (int)(t & 3);

    int li = eidx[e];
    int ri = eidx[(size_t)E + e];
    float w = efeat[e];

    float4 L = g_left_t[(size_t)li * 4 + j];
    float4 R = g_right_t[(size_t)ri * 4 + j];
    float4 We = W_edge4[j];

    float4 p;
    p.x = fmaxf(fmaf(w, We.x, L.x + R.x), 0.0f);
    p.y = fmaxf(fmaf(w, We.y, L.y + R.y), 0.0f);
    p.z = fmaxf(fmaf(w, We.z, L.z + R.z), 0.0f);
    p.w = fmaxf(fmaf(w, We.w, L.w + R.w), 0.0f);

    float4* dst = g_agg + (size_t)ri * 4 + j;
    asm volatile("red.global.add.v4.f32 [%0], {%1, %2, %3, %4};"
                 :: "l"(dst), "f"(p.x), "f"(p.y), "f"(p.z), "f"(p.w)
                 : "memory");
    if (j == 0) {
        asm volatile("red.global.add.f32 [%0], %1;"
                     :: "l"(g_deg + ri), "f"(1.0f)
                     : "memory");
    }
}

// ---------------------------------------------------------------------------
// Kernel 3: per-right-node tail.
//   aggregated = S @ W_final.T + deg * b_final
//   post = relu(aggregated) @ W_post.T + b_post
//   cat  = [post, right]
//   h    = relu(cat @ W_out1.T + b_out1)
//   out  = h @ W_out2.T + b_out2
// ---------------------------------------------------------------------------
__global__ void post_kernel(const float4* __restrict__ rightf,
                            const float* __restrict__ W_final, const float* __restrict__ b_final,
                            const float* __restrict__ W_post,  const float* __restrict__ b_post,
                            const float* __restrict__ W_out1,  const float* __restrict__ b_out1,
                            const float* __restrict__ W_out2,  const float* __restrict__ b_out2,
                            float4* __restrict__ out, int n_right) {
    __shared__ float sWf[256], sWp[256], sW1[512], sW2[256];
    __shared__ float sbf[16], sbp[16], sb1[16], sb2[16];
    for (int i = threadIdx.x; i < 256; i += blockDim.x) {
        sWf[i] = W_final[i];
        sWp[i] = W_post[i];
        sW2[i] = W_out2[i];
    }
    for (int i = threadIdx.x; i < 512; i += blockDim.x) sW1[i] = W_out1[i];
    if (threadIdx.x < 16) {
        sbf[threadIdx.x] = b_final[threadIdx.x];
        sbp[threadIdx.x] = b_post[threadIdx.x];
        sb1[threadIdx.x] = b_out1[threadIdx.x];
        sb2[threadIdx.x] = b_out2[threadIdx.x];
    }
    __syncthreads();

    int r = blockIdx.x * blockDim.x + threadIdx.x;
    if (r >= n_right) return;

    float S[EMB];
#pragma unroll
    for (int q = 0; q < 4; q++) {
        float4 v = g_agg[(size_t)r * 4 + q];
        S[4 * q + 0] = v.x; S[4 * q + 1] = v.y; S[4 * q + 2] = v.z; S[4 * q + 3] = v.w;
    }
    float d = g_deg[r];

    // aggregated = S @ W_final.T + d * b_final, then relu
    float a[EMB];
#pragma unroll
    for (int j = 0; j < EMB; j++) {
        float acc = d * sbf[j];
#pragma unroll
        for (int k = 0; k < EMB; k++) acc = fmaf(S[k], sWf[j * EMB + k], acc);
        a[j] = fmaxf(acc, 0.0f);
    }

    // post = a @ W_post.T + b_post
    float cat[2 * EMB];
#pragma unroll
    for (int j = 0; j < EMB; j++) {
        float acc = sbp[j];
#pragma unroll
        for (int k = 0; k < EMB; k++) acc = fmaf(a[k], sWp[j * EMB + k], acc);
        cat[j] = acc;
    }
    // cat second half = right features
#pragma unroll
    for (int q = 0; q < 4; q++) {
        float4 v = rightf[(size_t)r * 4 + q];
        cat[EMB + 4 * q + 0] = v.x; cat[EMB + 4 * q + 1] = v.y;
        cat[EMB + 4 * q + 2] = v.z; cat[EMB + 4 * q + 3] = v.w;
    }

    // h = relu(cat @ W_out1.T + b_out1)
    float h[EMB];
#pragma unroll
    for (int j = 0; j < EMB; j++) {
        float acc = sb1[j];
#pragma unroll
        for (int k = 0; k < 2 * EMB; k++) acc = fmaf(cat[k], sW1[j * 2 * EMB + k], acc);
        h[j] = fmaxf(acc, 0.0f);
    }

    // out = h @ W_out2.T + b_out2
#pragma unroll
    for (int q = 0; q < 4; q++) {
        float o[4];
#pragma unroll
        for (int c = 0; c < 4; c++) {
            int j = 4 * q + c;
            float acc = sb2[j];
#pragma unroll
            for (int k = 0; k < EMB; k++) acc = fmaf(h[k], sW2[j * EMB + k], acc);
            o[c] = acc;
        }
        float4 y;
        y.x = o[0]; y.y = o[1]; y.z = o[2]; y.w = o[3];
        out[(size_t)r * 4 + q] = y;
    }
}

// ---------------------------------------------------------------------------
extern "C" void kernel_launch(void* const* d_in, const int* in_sizes, int n_in,
                              void* d_out, int out_size) {
    const float* left    = (const float*)d_in[0];
    const float* efeat   = (const float*)d_in[1];
    const float* right   = (const float*)d_in[2];
    const int*   eidx    = (const int*)d_in[3];   // int32: JAX x64 disabled
    const float* W_left  = (const float*)d_in[4];
    const float* b_left  = (const float*)d_in[5];
    const float* W_edge  = (const float*)d_in[6];
    const float* W_right = (const float*)d_in[7];
    const float* W_final = (const float*)d_in[8];
    const float* b_final = (const float*)d_in[9];
    const float* W_post  = (const float*)d_in[10];
    const float* b_post  = (const float*)d_in[11];
    const float* W_out1  = (const float*)d_in[12];
    const float* b_out1  = (const float*)d_in[13];
    const float* W_out2  = (const float*)d_in[14];
    const float* b_out2  = (const float*)d_in[15];
    float* out = (float*)d_out;

    int n_left  = in_sizes[0] / EMB;
    int n_right = in_sizes[2] / EMB;
    int E       = in_sizes[1];

    void* agg_p = nullptr;
    void* deg_p = nullptr;
    cudaGetSymbolAddress(&agg_p, g_agg);
    cudaGetSymbolAddress(&deg_p, g_deg);
    cudaMemsetAsync(agg_p, 0, (size_t)n_right * EMB * sizeof(float));
    cudaMemsetAsync(deg_p, 0, (size_t)n_right * sizeof(float));

    int total_nodes = n_left + n_right;
    node_transform_kernel<<<(total_nodes + 255) / 256, 256>>>(
        (const float4*)left, (const float4*)right, W_left, b_left, W_right,
        n_left, n_right);

    long long edge_threads = (long long)E * 4;
    int edge_blocks = (int)((edge_threads + 255) / 256);
    edge_kernel<<<edge_blocks, 256>>>(eidx, efeat, (const float4*)W_edge, E);

    post_kernel<<<(n_right + 255) / 256, 256>>>(
        (const float4*)right, W_final, b_final, W_post, b_post,
        W_out1, b_out1, W_out2, b_out2, (float4*)out, n_right);
}

// round 5
// speedup vs baseline: 1.5441x; 1.5441x over previous
#include <cuda_runtime.h>
#include <cuda_bf16.h>
#include <cuda_fp16.h>

#define EMB 16
#define MAXN 200000
#define MAXE 4000000

// Scratch (device globals — no allocation allowed)
// Transformed node tables stored as fp16: 16 halves = 32 B/node = 2 x uint4.
__device__ uint4  g_left_h[MAXN * 2];    // [N_LEFT, 16] half
__device__ uint4  g_right_h[MAXN * 2];   // [N_RIGHT, 16] half
__device__ float4 g_agg[MAXN * 4];       // [N_RIGHT, 16] fp32 sum of relu(pre)
__device__ float  g_deg[MAXN];           // per-right-node degree (float)

// ---------------------------------------------------------------------------
// Kernel 1: node transforms.  left_t = L @ W_left.T + b_left ;  right_t = R @ W_right.T
// One thread per node; weights read as float4 from shared (LDS.128 broadcast);
// outputs converted to fp16 and stored as 2 x uint4.
// ---------------------------------------------------------------------------
__global__ void node_transform_kernel(const float4* __restrict__ left,
                                      const float4* __restrict__ right,
                                      const float4* __restrict__ W_left,
                                      const float* __restrict__ b_left,
                                      const float4* __restrict__ W_right,
                                      int n_left, int n_right) {
    __shared__ float4 sWl[EMB * 4];
    __shared__ float4 sWr[EMB * 4];
    __shared__ float  sbl[EMB];
    for (int i = threadIdx.x; i < EMB * 4; i += blockDim.x) {
        sWl[i] = W_left[i];
        sWr[i] = W_right[i];
    }
    if (threadIdx.x < EMB) sbl[threadIdx.x] = b_left[threadIdx.x];
    __syncthreads();

    int t = blockIdx.x * blockDim.x + threadIdx.x;
    if (t >= n_left + n_right) return;

    bool is_left = (t < n_left);
    int node = is_left ? t : (t - n_left);
    const float4* src = is_left ? (left + (size_t)node * 4) : (right + (size_t)node * 4);
    uint4* dst = is_left ? (g_left_h + (size_t)node * 2) : (g_right_h + (size_t)node * 2);
    const float4* W = is_left ? sWl : sWr;

    float4 x[4];
#pragma unroll
    for (int q = 0; q < 4; q++) x[q] = src[q];

    float y[EMB];
#pragma unroll
    for (int j = 0; j < EMB; j++) {
        float a = is_left ? sbl[j] : 0.0f;
#pragma unroll
        for (int q = 0; q < 4; q++) {
            float4 w = W[j * 4 + q];
            a = fmaf(x[q].x, w.x, a);
            a = fmaf(x[q].y, w.y, a);
            a = fmaf(x[q].z, w.z, a);
            a = fmaf(x[q].w, w.w, a);
        }
        y[j] = a;
    }

#pragma unroll
    for (int h = 0; h < 2; h++) {
        uint4 o;
        __half2 h0 = __floats2half2_rn(y[8 * h + 0], y[8 * h + 1]);
        __half2 h1 = __floats2half2_rn(y[8 * h + 2], y[8 * h + 3]);
        __half2 h2 = __floats2half2_rn(y[8 * h + 4], y[8 * h + 5]);
        __half2 h3 = __floats2half2_rn(y[8 * h + 6], y[8 * h + 7]);
        o.x = *(unsigned int*)&h0;
        o.y = *(unsigned int*)&h1;
        o.z = *(unsigned int*)&h2;
        o.w = *(unsigned int*)&h3;
        dst[h] = o;
    }
}

// ---------------------------------------------------------------------------
// Kernel 2: edge kernel.  2 lanes per edge; lane j handles 8 floats (one uint4
// of halves from each table).
//   pre = left_t[li] + w_e * W_edge + right_t[ri]  ->  relu  ->  2x red.v4 into agg[ri]
//   lane 0 also bumps degree.
// ---------------------------------------------------------------------------
__global__ void edge_kernel(const int* __restrict__ eidx,          // [2, E] int32
                            const float* __restrict__ efeat,       // [E]
                            const float4* __restrict__ W_edge4,    // 16 floats
                            int E) {
    long long t = (long long)blockIdx.x * blockDim.x + threadIdx.x;
    int e = (int)(t >> 1);
    if (e >= E) return;
    int j = (int)(t & 1);

    int li = eidx[e];
    int ri = eidx[(size_t)E + e];
    float w = efeat[e];

    uint4 Lu = g_left_h[(size_t)li * 2 + j];
    uint4 Ru = g_right_h[(size_t)ri * 2 + j];
    float4 We0 = W_edge4[2 * j];
    float4 We1 = W_edge4[2 * j + 1];

    float2 l0 = __half22float2(*(__half2*)&Lu.x);
    float2 l1 = __half22float2(*(__half2*)&Lu.y);
    float2 l2 = __half22float2(*(__half2*)&Lu.z);
    float2 l3 = __half22float2(*(__half2*)&Lu.w);
    float2 r0 = __half22float2(*(__half2*)&Ru.x);
    float2 r1 = __half22float2(*(__half2*)&Ru.y);
    float2 r2 = __half22float2(*(__half2*)&Ru.z);
    float2 r3 = __half22float2(*(__half2*)&Ru.w);

    float p0 = fmaxf(fmaf(w, We0.x, l0.x + r0.x), 0.0f);
    float p1 = fmaxf(fmaf(w, We0.y, l0.y + r0.y), 0.0f);
    float p2 = fmaxf(fmaf(w, We0.z, l1.x + r1.x), 0.0f);
    float p3 = fmaxf(fmaf(w, We0.w, l1.y + r1.y), 0.0f);
    float p4 = fmaxf(fmaf(w, We1.x, l2.x + r2.x), 0.0f);
    float p5 = fmaxf(fmaf(w, We1.y, l2.y + r2.y), 0.0f);
    float p6 = fmaxf(fmaf(w, We1.z, l3.x + r3.x), 0.0f);
    float p7 = fmaxf(fmaf(w, We1.w, l3.y + r3.y), 0.0f);

    float4* dst = g_agg + (size_t)ri * 4 + 2 * j;
    asm volatile("red.global.add.v4.f32 [%0], {%1, %2, %3, %4};"
                 :: "l"(dst), "f"(p0), "f"(p1), "f"(p2), "f"(p3)
                 : "memory");
    asm volatile("red.global.add.v4.f32 [%0], {%1, %2, %3, %4};"
                 :: "l"(dst + 1), "f"(p4), "f"(p5), "f"(p6), "f"(p7)
                 : "memory");
    if (j == 0) {
        asm volatile("red.global.add.f32 [%0], %1;"
                     :: "l"(g_deg + ri), "f"(1.0f)
                     : "memory");
    }
}

// ---------------------------------------------------------------------------
// Kernel 3: per-right-node tail (fp32 throughout).
// ---------------------------------------------------------------------------
__global__ void post_kernel(const float4* __restrict__ rightf,
                            const float* __restrict__ W_final, const float* __restrict__ b_final,
                            const float* __restrict__ W_post,  const float* __restrict__ b_post,
                            const float* __restrict__ W_out1,  const float* __restrict__ b_out1,
                            const float* __restrict__ W_out2,  const float* __restrict__ b_out2,
                            float4* __restrict__ out, int n_right) {
    __shared__ float sWf[256], sWp[256], sW1[512], sW2[256];
    __shared__ float sbf[16], sbp[16], sb1[16], sb2[16];
    for (int i = threadIdx.x; i < 256; i += blockDim.x) {
        sWf[i] = W_final[i];
        sWp[i] = W_post[i];
        sW2[i] = W_out2[i];
    }
    for (int i = threadIdx.x; i < 512; i += blockDim.x) sW1[i] = W_out1[i];
    if (threadIdx.x < 16) {
        sbf[threadIdx.x] = b_final[threadIdx.x];
        sbp[threadIdx.x] = b_post[threadIdx.x];
        sb1[threadIdx.x] = b_out1[threadIdx.x];
        sb2[threadIdx.x] = b_out2[threadIdx.x];
    }
    __syncthreads();

    int r = blockIdx.x * blockDim.x + threadIdx.x;
    if (r >= n_right) return;

    float S[EMB];
#pragma unroll
    for (int q = 0; q < 4; q++) {
        float4 v = g_agg[(size_t)r * 4 + q];
        S[4 * q + 0] = v.x; S[4 * q + 1] = v.y; S[4 * q + 2] = v.z; S[4 * q + 3] = v.w;
    }
    float d = g_deg[r];

    // aggregated = S @ W_final.T + d * b_final, then relu
    float a[EMB];
#pragma unroll
    for (int j = 0; j < EMB; j++) {
        float acc = d * sbf[j];
#pragma unroll
        for (int k = 0; k < EMB; k++) acc = fmaf(S[k], sWf[j * EMB + k], acc);
        a[j] = fmaxf(acc, 0.0f);
    }

    // post = a @ W_post.T + b_post ; cat = [post, right]
    float cat[2 * EMB];
#pragma unroll
    for (int j = 0; j < EMB; j++) {
        float acc = sbp[j];
#pragma unroll
        for (int k = 0; k < EMB; k++) acc = fmaf(a[k], sWp[j * EMB + k], acc);
        cat[j] = acc;
    }
#pragma unroll
    for (int q = 0; q < 4; q++) {
        float4 v = rightf[(size_t)r * 4 + q];
        cat[EMB + 4 * q + 0] = v.x; cat[EMB + 4 * q + 1] = v.y;
        cat[EMB + 4 * q + 2] = v.z; cat[EMB + 4 * q + 3] = v.w;
    }

    // h = relu(cat @ W_out1.T + b_out1)
    float h[EMB];
#pragma unroll
    for (int j = 0; j < EMB; j++) {
        float acc = sb1[j];
#pragma unroll
        for (int k = 0; k < 2 * EMB; k++) acc = fmaf(cat[k], sW1[j * 2 * EMB + k], acc);
        h[j] = fmaxf(acc, 0.0f);
    }

    // out = h @ W_out2.T + b_out2
#pragma unroll
    for (int q = 0; q < 4; q++) {
        float o[4];
#pragma unroll
        for (int c = 0; c < 4; c++) {
            int j = 4 * q + c;
            float acc = sb2[j];
#pragma unroll
            for (int k = 0; k < EMB; k++) acc = fmaf(h[k], sW2[j * EMB + k], acc);
            o[c] = acc;
        }
        float4 y;
        y.x = o[0]; y.y = o[1]; y.z = o[2]; y.w = o[3];
        out[(size_t)r * 4 + q] = y;
    }
}

// ---------------------------------------------------------------------------
extern "C" void kernel_launch(void* const* d_in, const int* in_sizes, int n_in,
                              void* d_out, int out_size) {
    const float* left    = (const float*)d_in[0];
    const float* efeat   = (const float*)d_in[1];
    const float* right   = (const float*)d_in[2];
    const int*   eidx    = (const int*)d_in[3];   // int32: JAX x64 disabled
    const float* W_left  = (const float*)d_in[4];
    const float* b_left  = (const float*)d_in[5];
    const float* W_edge  = (const float*)d_in[6];
    const float* W_right = (const float*)d_in[7];
    const float* W_final = (const float*)d_in[8];
    const float* b_final = (const float*)d_in[9];
    const float* W_post  = (const float*)d_in[10];
    const float* b_post  = (const float*)d_in[11];
    const float* W_out1  = (const float*)d_in[12];
    const float* b_out1  = (const float*)d_in[13];
    const float* W_out2  = (const float*)d_in[14];
    const float* b_out2  = (const float*)d_in[15];
    float* out = (float*)d_out;

    int n_left  = in_sizes[0] / EMB;
    int n_right = in_sizes[2] / EMB;
    int E       = in_sizes[1];

    void* agg_p = nullptr;
    void* deg_p = nullptr;
    cudaGetSymbolAddress(&agg_p, g_agg);
    cudaGetSymbolAddress(&deg_p, g_deg);
    cudaMemsetAsync(agg_p, 0, (size_t)n_right * EMB * sizeof(float));
    cudaMemsetAsync(deg_p, 0, (size_t)n_right * sizeof(float));

    int total_nodes = n_left + n_right;
    node_transform_kernel<<<(total_nodes + 255) / 256, 256>>>(
        (const float4*)left, (const float4*)right, (const float4*)W_left, b_left,
        (const float4*)W_right, n_left, n_right);

    long long edge_threads = (long long)E * 2;
    int edge_blocks = (int)((edge_threads + 255) / 256);
    edge_kernel<<<edge_blocks, 256>>>(eidx, efeat, (const float4*)W_edge, E);

    post_kernel<<<(n_right + 255) / 256, 256>>>(
        (const float4*)right, W_final, b_final, W_post, b_post,
        W_out1, b_out1, W_out2, b_out2, (float4*)out, n_right);
}